// round 12
// baseline (speedup 1.0000x reference)
#include <cuda_runtime.h>
#include <cuda_bf16.h>
#include <math.h>
#include <stdint.h>

#define HIDDEN 2048
#define BOT    64
#define NEXP   8
#define NTOK   16384

#define BM       32
#define BK       64
#define NTILES   (HIDDEN / BK)       // 32
#define THREADS  256
#define NBLK     (NTOK / BM)         // 512

// ---------------- dynamic smem layout (byte offsets) ---------------------------
#define A_HI(b)   ((b) * 4096)                // 2 x 4KB (32 rows x 128B bf16)
#define A_LO(b)   (8192 + (b) * 4096)         // 2 x 4KB
#define O_PART    0                           // 8KB k-partials (reuses A_HI region)
#define O_ZB      8192                        // 8704B z buffer [32][68] (reuses A_LO)
#define O_MU      16896                       // 32 f32
#define O_RS      17024
#define O_S       17152                       // 64 f32
#define O_T       17408
#define O_WUP     17664                       // 2KB raw w_up [8][64]
#define O_LG      19712                       // 1KB logits [32][8]
#define SMEM_TOTAL 20992
#define ZSTRIDE   68

#define SWZ128(off) ((off) ^ (((off) >> 3) & 0x70))

// ---------------- device scratch (no allocations allowed) ----------------------
// B in mma.sync fragment order: index = ((k16blk*8 + n8blk)*32 + lane)*2 + reg
__device__ uint32_t g_Bfh[128 * 8 * 32 * 2];   // 256KB hi fragments
__device__ uint32_t g_Bfl[128 * 8 * 32 * 2];   // 256KB lo fragments
__device__ float g_s[BOT];
__device__ float g_t[BOT];

// ---------------- PTX helpers ---------------------------------------------------
__device__ __forceinline__ uint32_t smem_u32(const void* p) {
    uint32_t a;
    asm("{ .reg .u64 t; cvta.to.shared.u64 t, %1; cvt.u32.u64 %0, t; }" : "=r"(a) : "l"(p));
    return a;
}
#define LDMX4(r, a) \
    asm volatile("ldmatrix.sync.aligned.m8n8.x4.shared.b16 {%0,%1,%2,%3}, [%4];" \
        : "=r"((r)[0]), "=r"((r)[1]), "=r"((r)[2]), "=r"((r)[3]) : "r"(a))

#define MMA16816(d, a, b0, b1) \
    asm volatile("mma.sync.aligned.m16n8k16.row.col.f32.bf16.bf16.f32 " \
        "{%0,%1,%2,%3}, {%4,%5,%6,%7}, {%8,%9}, {%0,%1,%2,%3};" \
        : "+f"((d)[0]), "+f"((d)[1]), "+f"((d)[2]), "+f"((d)[3]) \
        : "r"((a)[0]), "r"((a)[1]), "r"((a)[2]), "r"((a)[3]), "r"(b0), "r"(b1))

// ---------------- prep: G = gamma*W -> bf16 hi/lo in FRAGMENT order -------------
__global__ void prep_kernel(const float* __restrict__ w_down,
                            const float* __restrict__ gamma,
                            const float* __restrict__ beta)
{
    __shared__ float red_s[8], red_t[8];
    const int n   = blockIdx.x;           // 0..63
    const int tid = threadIdx.x;          // 256
    const int k0  = tid * 8;

    float w[8], gv[8], bv[8];
    *(float4*)&w[0]  = *(const float4*)(w_down + n * HIDDEN + k0);
    *(float4*)&w[4]  = *(const float4*)(w_down + n * HIDDEN + k0 + 4);
    *(float4*)&gv[0] = *(const float4*)(gamma + k0);
    *(float4*)&gv[4] = *(const float4*)(gamma + k0 + 4);
    *(float4*)&bv[0] = *(const float4*)(beta + k0);
    *(float4*)&bv[4] = *(const float4*)(beta + k0 + 4);

    float ps = 0.f, pt = 0.f;
    uint32_t hw[4], lw[4];
    #pragma unroll
    for (int p = 0; p < 4; p++) {
        float g0 = gv[2*p] * w[2*p];
        float g1 = gv[2*p+1] * w[2*p+1];
        ps += g0 + g1;
        pt = fmaf(bv[2*p], w[2*p], pt);
        pt = fmaf(bv[2*p+1], w[2*p+1], pt);
        __nv_bfloat162 h = __floats2bfloat162_rn(g0, g1);
        float r0 = g0 - __bfloat162float(h.x);
        float r1 = g1 - __bfloat162float(h.y);
        __nv_bfloat162 l = __floats2bfloat162_rn(r0, r1);
        hw[p] = *(uint32_t*)&h;
        lw[p] = *(uint32_t*)&l;
    }
    {
        const int k16  = k0 >> 4;
        const int n8   = n >> 3;
        const int l0   = (n & 7) * 4;
        const int reg  = (k0 >> 3) & 1;
        const int base = ((k16 * 8 + n8) * 32 + l0) * 2 + reg;
        #pragma unroll
        for (int p = 0; p < 4; p++) {
            g_Bfh[base + p * 2] = hw[p];
            g_Bfl[base + p * 2] = lw[p];
        }
    }

    #pragma unroll
    for (int o = 16; o > 0; o >>= 1) {
        ps += __shfl_xor_sync(0xffffffffu, ps, o);
        pt += __shfl_xor_sync(0xffffffffu, pt, o);
    }
    int wi = tid >> 5, lane = tid & 31;
    if (lane == 0) { red_s[wi] = ps; red_t[wi] = pt; }
    __syncthreads();
    if (tid == 0) {
        float ss = 0.f, tt = 0.f;
        #pragma unroll
        for (int i = 0; i < 8; i++) { ss += red_s[i]; tt += red_t[i]; }
        g_s[n] = ss; g_t[n] = tt;
    }
}

// ---------------- main fused HMMA kernel ----------------------------------------
extern __shared__ char dsm[];

__global__ __launch_bounds__(THREADS, 3)
void router_kernel(const float* __restrict__ H,      // [16384][2048]
                   const float* __restrict__ w_up,   // [8][64]
                   float* __restrict__ out)          // [16384][8]
{
    const uint32_t sb  = smem_u32(dsm);
    const int tid  = threadIdx.x;
    const int wid  = tid >> 5;
    const int lane = tid & 31;
    const int pos  = wid & 3;             // warp position: 2m x 2n
    const int wm   = pos & 1;             // rows wm*16..+16
    const int wn   = pos >> 1;            // cols wn*32..+32
    const int kh   = wid >> 2;            // k-half within tile

    // small tables
    ((float*)(dsm + O_WUP))[tid]       = w_up[tid];
    ((float*)(dsm + O_WUP))[tid + 256] = w_up[tid + 256];
    if (tid < BOT) {
        ((float*)(dsm + O_S))[tid] = g_s[tid];
        ((float*)(dsm + O_T))[tid] = g_t[tid];
    }

    // A geometry: 2 float4/thread/tile; row = tid>>3, k = (tid&7)*8..+8
    const int lrow = tid >> 3;            // 0..31
    const float* Hbase = H + ((size_t)blockIdx.x * BM + lrow) * HIDDEN + (tid & 7) * 8;
    const uint32_t sts_sw = SWZ128((uint32_t)(lrow * 128 + (tid & 7) * 16));

    // Hoisted A-LDSM offset
    const uint32_t half16 = (uint32_t)((lane >> 4) * 16);
    const uint32_t aoff = SWZ128((uint32_t)((wm * 16 + (lane & 15)) * 128)) ^ half16;

    // B fragment base for this warp (per tile: + t*2048 words)
    const uint32_t bfbase = (uint32_t)(((kh * 2) * 8 + wn * 4) * 32 + lane) * 2;

    float acc[4][4];                     // [n8][reg] for 16x32 warp tile
    #pragma unroll
    for (int ni = 0; ni < 4; ni++)
        #pragma unroll
        for (int r = 0; r < 4; r++) acc[ni][r] = 0.f;

    float psum = 0.f, psq = 0.f;
    float4 pf[2];

    // ---- prologue: A0 -> regs -> convert -> smem(0); A1 -> pf ----
    pf[0] = *(const float4*)(Hbase);
    pf[1] = *(const float4*)(Hbase + 4);
    {
        #pragma unroll
        for (int j = 0; j < 2; j++) {
            float4 v = pf[j];
            psum += (v.x + v.y) + (v.z + v.w);
            psq  = fmaf(v.x, v.x, psq); psq = fmaf(v.y, v.y, psq);
            psq  = fmaf(v.z, v.z, psq); psq = fmaf(v.w, v.w, psq);
        }
        __nv_bfloat162 h01 = __floats2bfloat162_rn(pf[0].x, pf[0].y);
        __nv_bfloat162 h23 = __floats2bfloat162_rn(pf[0].z, pf[0].w);
        __nv_bfloat162 h45 = __floats2bfloat162_rn(pf[1].x, pf[1].y);
        __nv_bfloat162 h67 = __floats2bfloat162_rn(pf[1].z, pf[1].w);
        __nv_bfloat162 l01 = __floats2bfloat162_rn(pf[0].x - __bfloat162float(h01.x), pf[0].y - __bfloat162float(h01.y));
        __nv_bfloat162 l23 = __floats2bfloat162_rn(pf[0].z - __bfloat162float(h23.x), pf[0].w - __bfloat162float(h23.y));
        __nv_bfloat162 l45 = __floats2bfloat162_rn(pf[1].x - __bfloat162float(h45.x), pf[1].y - __bfloat162float(h45.y));
        __nv_bfloat162 l67 = __floats2bfloat162_rn(pf[1].z - __bfloat162float(h67.x), pf[1].w - __bfloat162float(h67.y));
        *(uint4*)(dsm + A_HI(0) + sts_sw) =
            make_uint4(*(uint32_t*)&h01, *(uint32_t*)&h23, *(uint32_t*)&h45, *(uint32_t*)&h67);
        *(uint4*)(dsm + A_LO(0) + sts_sw) =
            make_uint4(*(uint32_t*)&l01, *(uint32_t*)&l23, *(uint32_t*)&l45, *(uint32_t*)&l67);
    }
    pf[0] = *(const float4*)(Hbase + BK);
    pf[1] = *(const float4*)(Hbase + BK + 4);
    __syncthreads();            // tile 0 A visible

    #pragma unroll 1
    for (int t = 0; t < NTILES; t++) {
        const int buf = t & 1, nb = buf ^ 1;
        // ---- B fragments for tile t: coalesced LDG.64 (L1-resident across warps/CTAs)
        uint2 bh2[2][4], bl2[2][4];
        {
            const uint32_t tb = bfbase + (uint32_t)t * 2048;
            #pragma unroll
            for (int ss = 0; ss < 2; ss++) {
                const uint32_t o = tb + (uint32_t)ss * 512;
                #pragma unroll
                for (int j = 0; j < 4; j++) {
                    bh2[ss][j] = *(const uint2*)&g_Bfh[o + j * 64];
                    bl2[ss][j] = *(const uint2*)&g_Bfl[o + j * 64];
                }
            }
        }
        // ---- MMA phase for tile t on buf (3-pass hi/lo, split-k) ----
        {
            const uint32_t ab_hi = sb + A_HI(buf), ab_lo = sb + A_LO(buf);
            #pragma unroll
            for (int ss = 0; ss < 2; ss++) {
                const uint32_t ks = (uint32_t)(kh * 64 + ss * 32);
                uint32_t ah[4], al[4];
                LDMX4(ah, ab_hi + (aoff ^ ks));
                LDMX4(al, ab_lo + (aoff ^ ks));
                #pragma unroll
                for (int ni = 0; ni < 4; ni++) {
                    MMA16816(acc[ni], ah, bh2[ss][ni].x, bh2[ss][ni].y);
                    MMA16816(acc[ni], ah, bl2[ss][ni].x, bl2[ss][ni].y);
                    MMA16816(acc[ni], al, bh2[ss][ni].x, bh2[ss][ni].y);
                }
            }
        }
        // ---- convert A_{t+1} -> nb (overlaps tensor work of tile t) ----
        if (t + 1 < NTILES) {
            #pragma unroll
            for (int j = 0; j < 2; j++) {
                float4 v = pf[j];
                psum += (v.x + v.y) + (v.z + v.w);
                psq  = fmaf(v.x, v.x, psq); psq = fmaf(v.y, v.y, psq);
                psq  = fmaf(v.z, v.z, psq); psq = fmaf(v.w, v.w, psq);
            }
            __nv_bfloat162 h01 = __floats2bfloat162_rn(pf[0].x, pf[0].y);
            __nv_bfloat162 h23 = __floats2bfloat162_rn(pf[0].z, pf[0].w);
            __nv_bfloat162 h45 = __floats2bfloat162_rn(pf[1].x, pf[1].y);
            __nv_bfloat162 h67 = __floats2bfloat162_rn(pf[1].z, pf[1].w);
            __nv_bfloat162 l01 = __floats2bfloat162_rn(pf[0].x - __bfloat162float(h01.x), pf[0].y - __bfloat162float(h01.y));
            __nv_bfloat162 l23 = __floats2bfloat162_rn(pf[0].z - __bfloat162float(h23.x), pf[0].w - __bfloat162float(h23.y));
            __nv_bfloat162 l45 = __floats2bfloat162_rn(pf[1].x - __bfloat162float(h45.x), pf[1].y - __bfloat162float(h45.y));
            __nv_bfloat162 l67 = __floats2bfloat162_rn(pf[1].z - __bfloat162float(h67.x), pf[1].w - __bfloat162float(h67.y));
            *(uint4*)(dsm + A_HI(nb) + sts_sw) =
                make_uint4(*(uint32_t*)&h01, *(uint32_t*)&h23, *(uint32_t*)&h45, *(uint32_t*)&h67);
            *(uint4*)(dsm + A_LO(nb) + sts_sw) =
                make_uint4(*(uint32_t*)&l01, *(uint32_t*)&l23, *(uint32_t*)&l45, *(uint32_t*)&l67);
        }
        // ---- prefetch A_{t+2} (pf free; >1 iteration of slack) ----
        if (t + 2 < NTILES) {
            const float* hp = Hbase + (t + 2) * BK;
            pf[0] = *(const float4*)(hp);
            pf[1] = *(const float4*)(hp + 4);
        }
        __syncthreads();            // tile t A reads done; tile t+1 A visible
    }

    // ---- kh=1 warps dump k-partials (once per CTA) ----
    if (kh == 1) {
        float* pp = (float*)(dsm + O_PART) + pos * 512;
        #pragma unroll
        for (int ni = 0; ni < 4; ni++)
            #pragma unroll
            for (int r = 0; r < 4; r++)
                pp[(ni * 4 + r) * 32 + lane] = acc[ni][r];
    }

    // ---- LN stats: groups of 8 consecutive lanes share a row ----
    #pragma unroll
    for (int o = 1; o < 8; o <<= 1) {
        psum += __shfl_xor_sync(0xffffffffu, psum, o);
        psq  += __shfl_xor_sync(0xffffffffu, psq, o);
    }
    if ((tid & 7) == 0) {
        float mu  = psum * (1.f / HIDDEN);
        float var = psq * (1.f / HIDDEN) - mu * mu;
        ((float*)(dsm + O_MU))[lrow] = mu;
        ((float*)(dsm + O_RS))[lrow] = rsqrtf(var + 1e-5f);
    }
    __syncthreads();

    // ---- kh=0 warps: merge partials, LN-correct + SiLU -> z buffer ----
    if (kh == 0) {
        float* zb = (float*)(dsm + O_ZB);    // [32][68]
        const float* pp  = (const float*)(dsm + O_PART) + pos * 512;
        const float* muA = (const float*)(dsm + O_MU);
        const float* rsA = (const float*)(dsm + O_RS);
        const float* sA  = (const float*)(dsm + O_S);
        const float* tA  = (const float*)(dsm + O_T);
        int r0 = wm * 16 + (lane >> 2);
        float mu0 = muA[r0], rs0 = rsA[r0];
        float mu1 = muA[r0 + 8], rs1 = rsA[r0 + 8];
        #pragma unroll
        for (int ni = 0; ni < 4; ni++) {
            const float* pf4 = pp + (ni * 4) * 32 + lane;
            float a0 = acc[ni][0] + pf4[0];
            float a1 = acc[ni][1] + pf4[32];
            float a2 = acc[ni][2] + pf4[64];
            float a3 = acc[ni][3] + pf4[96];
            int c0 = wn * 32 + ni * 8 + (lane & 3) * 2;
            float s0 = sA[c0], s1 = sA[c0 + 1];
            float t0 = tA[c0], t1 = tA[c0 + 1];
            float p00 = rs0 * (a0 - mu0 * s0) + t0;
            float p01 = rs0 * (a1 - mu0 * s1) + t1;
            float p10 = rs1 * (a2 - mu1 * s0) + t0;
            float p11 = rs1 * (a3 - mu1 * s1) + t1;
            float z00 = p00 / (1.f + __expf(-p00));
            float z01 = p01 / (1.f + __expf(-p01));
            float z10 = p10 / (1.f + __expf(-p10));
            float z11 = p11 / (1.f + __expf(-p11));
            *(float2*)&zb[r0 * ZSTRIDE + c0]       = make_float2(z00, z01);
            *(float2*)&zb[(r0 + 8) * ZSTRIDE + c0] = make_float2(z10, z11);
        }
    }
    __syncthreads();

    // ---- router GEMM: thread = (token m = tid>>3, expert e = tid&7) ----
    {
        const int m = tid >> 3, e = tid & 7;
        const float* zr = (const float*)(dsm + O_ZB) + m * ZSTRIDE;
        const float* w0 = (const float*)(dsm + O_WUP) + e * 64;
        float l0 = 0.f;
        #pragma unroll
        for (int d4 = 0; d4 < 16; d4++) {
            float4 zv = ((const float4*)zr)[d4];
            float4 wa = ((const float4*)w0)[d4];
            l0 = fmaf(zv.x, wa.x, l0); l0 = fmaf(zv.y, wa.y, l0);
            l0 = fmaf(zv.z, wa.z, l0); l0 = fmaf(zv.w, wa.w, l0);
        }
        ((float*)(dsm + O_LG))[m * 8 + e] = l0;
    }
    __syncthreads();

    // ---- top-2 softmax (first-index tie-break matches jax.lax.top_k) ----
    if (tid < BM) {
        const float* lp = (const float*)(dsm + O_LG) + tid * 8;
        float lg[8];
        #pragma unroll
        for (int e = 0; e < 8; e++) lg[e] = lp[e];
        int i1 = 0; float m1 = lg[0];
        #pragma unroll
        for (int e = 1; e < 8; e++) if (lg[e] > m1) { m1 = lg[e]; i1 = e; }
        int i2 = -1; float m2 = -3.4e38f;
        #pragma unroll
        for (int e = 0; e < 8; e++) if (e != i1 && lg[e] > m2) { m2 = lg[e]; i2 = e; }
        float p1 = 1.f / (1.f + __expf(m2 - m1));
        float p2 = 1.f - p1;
        float o[8];
        #pragma unroll
        for (int e = 0; e < 8; e++) o[e] = (e == i1) ? p1 : (e == i2) ? p2 : 0.f;
        float* op = out + ((size_t)blockIdx.x * BM + tid) * NEXP;
        *(float4*)op       = make_float4(o[0], o[1], o[2], o[3]);
        *(float4*)(op + 4) = make_float4(o[4], o[5], o[6], o[7]);
    }
}

// ---------------- launch --------------------------------------------------------
extern "C" void kernel_launch(void* const* d_in, const int* in_sizes, int n_in,
                              void* d_out, int out_size)
{
    (void)in_sizes; (void)n_in; (void)out_size;
    const float* hs     = (const float*)d_in[0];
    const float* w_down = (const float*)d_in[1];
    const float* w_up   = (const float*)d_in[2];
    const float* gamma  = (const float*)d_in[3];
    const float* beta   = (const float*)d_in[4];
    float* out = (float*)d_out;

    static int attr_done = 0;
    if (!attr_done) {
        cudaFuncSetAttribute(router_kernel, cudaFuncAttributeMaxDynamicSharedMemorySize, SMEM_TOTAL);
        attr_done = 1;
    }
    prep_kernel<<<BOT, THREADS>>>(w_down, gamma, beta);
    router_kernel<<<NBLK, THREADS, SMEM_TOTAL>>>(hs, w_up, out);
}

// round 13
// speedup vs baseline: 1.4797x; 1.4797x over previous
#include <cuda_runtime.h>
#include <cuda_bf16.h>
#include <math.h>
#include <stdint.h>

#define HIDDEN 2048
#define BOT    64
#define NEXP   8
#define NTOK   16384

#define BM       64
#define BK       64
#define NTILES   (HIDDEN / BK)       // 32
#define THREADS  256
#define NBLK     (NTOK / BM)         // 256

// ---------------- dynamic smem layout (byte offsets) ---------------------------
#define O_PART    0                           // 16KB kh=1 partials (4 wm x 4KB)
#define O_ZB      16384                       // 17408B z buffer [64][68]
#define O_SSUM    33792                       // [2][64] f32 LN sum partials
#define O_SSQ     34304                       // [2][64] f32
#define O_MU      34816                       // 64 f32
#define O_RS      35072
#define O_S       35328
#define O_T       35584
#define O_WUP     35840                       // 2KB raw w_up [8][64]
#define O_LG      37888                       // 2KB logits [64][8]
#define SMEM_TOTAL 39936
#define ZSTRIDE   68

#define SWZ128(off) ((off) ^ (((off) >> 3) & 0x70))

// ---------------- device scratch (no allocations allowed) ----------------------
// B in mma.sync fragment order: index = ((k16blk*8 + n8blk)*32 + lane)*2 + reg
__device__ uint32_t g_Bfh[128 * 8 * 32 * 2];   // 256KB hi fragments
__device__ uint32_t g_Bfl[128 * 8 * 32 * 2];   // 256KB lo fragments
__device__ float g_s[BOT];
__device__ float g_t[BOT];

// ---------------- PTX helpers ---------------------------------------------------
#define MMA16816(d, a0, a1, a2, a3, b0, b1) \
    asm volatile("mma.sync.aligned.m16n8k16.row.col.f32.bf16.bf16.f32 " \
        "{%0,%1,%2,%3}, {%4,%5,%6,%7}, {%8,%9}, {%0,%1,%2,%3};" \
        : "+f"((d)[0]), "+f"((d)[1]), "+f"((d)[2]), "+f"((d)[3]) \
        : "r"(a0), "r"(a1), "r"(a2), "r"(a3), "r"(b0), "r"(b1))

__device__ __forceinline__ uint32_t bf2_hi(float2 v) {
    __nv_bfloat162 h = __floats2bfloat162_rn(v.x, v.y);
    return *(uint32_t*)&h;
}
__device__ __forceinline__ uint32_t bf2_lo(float2 v, uint32_t h) {
    float hx = __uint_as_float(h << 16);
    float hy = __uint_as_float(h & 0xffff0000u);
    __nv_bfloat162 l = __floats2bfloat162_rn(v.x - hx, v.y - hy);
    return *(uint32_t*)&l;
}

// ---------------- prep: G = gamma*W -> bf16 hi/lo in FRAGMENT order -------------
__global__ void prep_kernel(const float* __restrict__ w_down,
                            const float* __restrict__ gamma,
                            const float* __restrict__ beta)
{
    __shared__ float red_s[8], red_t[8];
    const int n   = blockIdx.x;           // 0..63
    const int tid = threadIdx.x;          // 256
    const int k0  = tid * 8;

    float w[8], gv[8], bv[8];
    *(float4*)&w[0]  = *(const float4*)(w_down + n * HIDDEN + k0);
    *(float4*)&w[4]  = *(const float4*)(w_down + n * HIDDEN + k0 + 4);
    *(float4*)&gv[0] = *(const float4*)(gamma + k0);
    *(float4*)&gv[4] = *(const float4*)(gamma + k0 + 4);
    *(float4*)&bv[0] = *(const float4*)(beta + k0);
    *(float4*)&bv[4] = *(const float4*)(beta + k0 + 4);

    float ps = 0.f, pt = 0.f;
    uint32_t hw[4], lw[4];
    #pragma unroll
    for (int p = 0; p < 4; p++) {
        float g0 = gv[2*p] * w[2*p];
        float g1 = gv[2*p+1] * w[2*p+1];
        ps += g0 + g1;
        pt = fmaf(bv[2*p], w[2*p], pt);
        pt = fmaf(bv[2*p+1], w[2*p+1], pt);
        __nv_bfloat162 h = __floats2bfloat162_rn(g0, g1);
        float r0 = g0 - __bfloat162float(h.x);
        float r1 = g1 - __bfloat162float(h.y);
        __nv_bfloat162 l = __floats2bfloat162_rn(r0, r1);
        hw[p] = *(uint32_t*)&h;
        lw[p] = *(uint32_t*)&l;
    }
    {
        const int k16  = k0 >> 4;
        const int n8   = n >> 3;
        const int l0   = (n & 7) * 4;
        const int reg  = (k0 >> 3) & 1;
        const int base = ((k16 * 8 + n8) * 32 + l0) * 2 + reg;
        #pragma unroll
        for (int p = 0; p < 4; p++) {
            g_Bfh[base + p * 2] = hw[p];
            g_Bfl[base + p * 2] = lw[p];
        }
    }

    #pragma unroll
    for (int o = 16; o > 0; o >>= 1) {
        ps += __shfl_xor_sync(0xffffffffu, ps, o);
        pt += __shfl_xor_sync(0xffffffffu, pt, o);
    }
    int wi = tid >> 5, lane = tid & 31;
    if (lane == 0) { red_s[wi] = ps; red_t[wi] = pt; }
    __syncthreads();
    if (tid == 0) {
        float ss = 0.f, tt = 0.f;
        #pragma unroll
        for (int i = 0; i < 8; i++) { ss += red_s[i]; tt += red_t[i]; }
        g_s[n] = ss; g_t[n] = tt;
    }
}

// ---------------- main fused HMMA kernel (barrier-free mainloop) ----------------
extern __shared__ char dsm[];

__global__ __launch_bounds__(THREADS, 2)
void router_kernel(const float* __restrict__ H,      // [16384][2048]
                   const float* __restrict__ w_up,   // [8][64]
                   float* __restrict__ out)          // [16384][8]
{
    const int tid  = threadIdx.x;
    const int wid  = tid >> 5;
    const int lane = tid & 31;
    const int wm   = wid & 3;             // rows wm*16..+16 (warp tile 16m x 64n)
    const int kh   = wid >> 2;            // k-half [kh*32, kh*32+32) per tile
    const int qr   = lane >> 2;           // 0..7
    const int qc   = lane & 3;            // 0..3

    // small tables
    ((float*)(dsm + O_WUP))[tid]       = w_up[tid];
    ((float*)(dsm + O_WUP))[tid + 256] = w_up[tid + 256];
    if (tid < BOT) {
        ((float*)(dsm + O_S))[tid] = g_s[tid];
        ((float*)(dsm + O_T))[tid] = g_t[tid];
    }

    // A fragment-direct geometry: rows r0 = wm*16+qr, r1 = r0+8;
    // k per tile: kh*32 + {qc*2, qc*2+8} (ss0), +16, +24 (ss1)
    const float* p0 = H + ((size_t)blockIdx.x * BM + wm * 16 + qr) * HIDDEN + kh * 32 + qc * 2;
    const float* p1 = p0 + 8 * HIDDEN;

    // B fragment base (per tile t: word offset (t*4 + kh*2 + ss)*512)
    const uint32_t bfb = (uint32_t)(((kh * 2) * 8) * 32 + lane) * 2;

    float acc[8][4];                     // [n8][reg] for 16m x 64n warp tile
    #pragma unroll
    for (int ni = 0; ni < 8; ni++)
        #pragma unroll
        for (int r = 0; r < 4; r++) acc[ni][r] = 0.f;

    float psum0 = 0.f, psum1 = 0.f, psq0 = 0.f, psq1 = 0.f;

    // pf[ss*4+j]: j0 = (r0, k+0), j1 = (r1, k+0), j2 = (r0, k+8), j3 = (r1, k+8)
    float2 pf[8];
    #pragma unroll
    for (int s = 0; s < 2; s++) {
        pf[s*4+0] = *(const float2*)(p0 + s * 16);
        pf[s*4+1] = *(const float2*)(p1 + s * 16);
        pf[s*4+2] = *(const float2*)(p0 + s * 16 + 8);
        pf[s*4+3] = *(const float2*)(p1 + s * 16 + 8);
    }

    #pragma unroll 1
    for (int t = 0; t < NTILES; t++) {
        // ---- convert pf -> A fragments (both k16 steps) + LN stats ----
        uint32_t ah[2][4], al[2][4];
        #pragma unroll
        for (int s = 0; s < 2; s++) {
            #pragma unroll
            for (int j = 0; j < 4; j++) {
                float2 v = pf[s*4+j];
                ah[s][j] = bf2_hi(v);
                al[s][j] = bf2_lo(v, ah[s][j]);
            }
            psum0 += (pf[s*4+0].x + pf[s*4+0].y) + (pf[s*4+2].x + pf[s*4+2].y);
            psum1 += (pf[s*4+1].x + pf[s*4+1].y) + (pf[s*4+3].x + pf[s*4+3].y);
            psq0 = fmaf(pf[s*4+0].x, pf[s*4+0].x, psq0); psq0 = fmaf(pf[s*4+0].y, pf[s*4+0].y, psq0);
            psq0 = fmaf(pf[s*4+2].x, pf[s*4+2].x, psq0); psq0 = fmaf(pf[s*4+2].y, pf[s*4+2].y, psq0);
            psq1 = fmaf(pf[s*4+1].x, pf[s*4+1].x, psq1); psq1 = fmaf(pf[s*4+1].y, pf[s*4+1].y, psq1);
            psq1 = fmaf(pf[s*4+3].x, pf[s*4+3].x, psq1); psq1 = fmaf(pf[s*4+3].y, pf[s*4+3].y, psq1);
        }
        // ---- prefetch A f32 for tile t+1 (consumed next iteration) ----
        if (t + 1 < NTILES) {
            const float* q0 = p0 + (t + 1) * BK;
            const float* q1 = p1 + (t + 1) * BK;
            #pragma unroll
            for (int s = 0; s < 2; s++) {
                pf[s*4+0] = *(const float2*)(q0 + s * 16);
                pf[s*4+1] = *(const float2*)(q1 + s * 16);
                pf[s*4+2] = *(const float2*)(q0 + s * 16 + 8);
                pf[s*4+3] = *(const float2*)(q1 + s * 16 + 8);
            }
        }
        // ---- B fragments + MMA, per k16 step (3-pass hi/lo) ----
        #pragma unroll
        for (int s = 0; s < 2; s++) {
            const uint32_t bb = bfb + (uint32_t)(t * 4 + s) * 512;
            uint2 bh[8], bl[8];
            #pragma unroll
            for (int ni = 0; ni < 8; ni++) {
                bh[ni] = *(const uint2*)&g_Bfh[bb + ni * 64];
                bl[ni] = *(const uint2*)&g_Bfl[bb + ni * 64];
            }
            #pragma unroll
            for (int ni = 0; ni < 8; ni++) {
                MMA16816(acc[ni], ah[s][0], ah[s][1], ah[s][2], ah[s][3], bh[ni].x, bh[ni].y);
                MMA16816(acc[ni], ah[s][0], ah[s][1], ah[s][2], ah[s][3], bl[ni].x, bl[ni].y);
                MMA16816(acc[ni], al[s][0], al[s][1], al[s][2], al[s][3], bh[ni].x, bh[ni].y);
            }
        }
    }

    // ---- epilogue: kh=1 dumps partials; stats partials to smem ----
    if (kh == 1) {
        float* pp = (float*)(dsm + O_PART) + wm * 1024;
        #pragma unroll
        for (int ni = 0; ni < 8; ni++)
            #pragma unroll
            for (int r = 0; r < 4; r++)
                pp[(ni * 4 + r) * 32 + lane] = acc[ni][r];
    }
    // LN stat partials: reduce over qc lanes (xor 1,2), write per (kh,row)
    #pragma unroll
    for (int o = 1; o < 4; o <<= 1) {
        psum0 += __shfl_xor_sync(0xffffffffu, psum0, o);
        psum1 += __shfl_xor_sync(0xffffffffu, psum1, o);
        psq0  += __shfl_xor_sync(0xffffffffu, psq0, o);
        psq1  += __shfl_xor_sync(0xffffffffu, psq1, o);
    }
    if (qc == 0) {
        int rbase = wm * 16 + qr;
        ((float*)(dsm + O_SSUM))[kh * 64 + rbase]     = psum0;
        ((float*)(dsm + O_SSUM))[kh * 64 + rbase + 8] = psum1;
        ((float*)(dsm + O_SSQ))[kh * 64 + rbase]      = psq0;
        ((float*)(dsm + O_SSQ))[kh * 64 + rbase + 8]  = psq1;
    }
    __syncthreads();

    if (tid < BM) {
        float su = ((float*)(dsm + O_SSUM))[tid] + ((float*)(dsm + O_SSUM))[64 + tid];
        float sq = ((float*)(dsm + O_SSQ))[tid]  + ((float*)(dsm + O_SSQ))[64 + tid];
        float mu  = su * (1.f / HIDDEN);
        float var = sq * (1.f / HIDDEN) - mu * mu;
        ((float*)(dsm + O_MU))[tid] = mu;
        ((float*)(dsm + O_RS))[tid] = rsqrtf(var + 1e-5f);
    }
    __syncthreads();

    // ---- kh=0: merge partials, LN-correct + SiLU -> z buffer ----
    if (kh == 0) {
        float* zb = (float*)(dsm + O_ZB);    // [64][68]
        const float* pp  = (const float*)(dsm + O_PART) + wm * 1024;
        const float* muA = (const float*)(dsm + O_MU);
        const float* rsA = (const float*)(dsm + O_RS);
        const float* sA  = (const float*)(dsm + O_S);
        const float* tA  = (const float*)(dsm + O_T);
        int r0 = wm * 16 + qr;
        float mu0 = muA[r0], rs0 = rsA[r0];
        float mu1 = muA[r0 + 8], rs1 = rsA[r0 + 8];
        #pragma unroll
        for (int ni = 0; ni < 8; ni++) {
            const float* pf4 = pp + (ni * 4) * 32 + lane;
            float a0 = acc[ni][0] + pf4[0];
            float a1 = acc[ni][1] + pf4[32];
            float a2 = acc[ni][2] + pf4[64];
            float a3 = acc[ni][3] + pf4[96];
            int c0 = ni * 8 + qc * 2;
            float s0 = sA[c0], s1 = sA[c0 + 1];
            float t0 = tA[c0], t1 = tA[c0 + 1];
            float p00 = rs0 * (a0 - mu0 * s0) + t0;
            float p01 = rs0 * (a1 - mu0 * s1) + t1;
            float p10 = rs1 * (a2 - mu1 * s0) + t0;
            float p11 = rs1 * (a3 - mu1 * s1) + t1;
            float z00 = p00 / (1.f + __expf(-p00));
            float z01 = p01 / (1.f + __expf(-p01));
            float z10 = p10 / (1.f + __expf(-p10));
            float z11 = p11 / (1.f + __expf(-p11));
            *(float2*)&zb[r0 * ZSTRIDE + c0]       = make_float2(z00, z01);
            *(float2*)&zb[(r0 + 8) * ZSTRIDE + c0] = make_float2(z10, z11);
        }
    }
    __syncthreads();

    // ---- router GEMM: thread = (token m, expert pair eg) ----
    {
        const int m = tid & 63, eg = tid >> 6;
        const float* zr = (const float*)(dsm + O_ZB) + m * ZSTRIDE;
        const float* w0 = (const float*)(dsm + O_WUP) + eg * 128;
        const float* w1 = w0 + 64;
        float l0 = 0.f, l1 = 0.f;
        #pragma unroll
        for (int d4 = 0; d4 < 16; d4++) {
            float4 zv = ((const float4*)zr)[d4];
            float4 wa = ((const float4*)w0)[d4];
            float4 wb = ((const float4*)w1)[d4];
            l0 = fmaf(zv.x, wa.x, l0); l0 = fmaf(zv.y, wa.y, l0);
            l0 = fmaf(zv.z, wa.z, l0); l0 = fmaf(zv.w, wa.w, l0);
            l1 = fmaf(zv.x, wb.x, l1); l1 = fmaf(zv.y, wb.y, l1);
            l1 = fmaf(zv.z, wb.z, l1); l1 = fmaf(zv.w, wb.w, l1);
        }
        ((float*)(dsm + O_LG))[m * 8 + eg * 2]     = l0;
        ((float*)(dsm + O_LG))[m * 8 + eg * 2 + 1] = l1;
    }
    __syncthreads();

    // ---- top-2 softmax (first-index tie-break matches jax.lax.top_k) ----
    if (tid < BM) {
        const float* lp = (const float*)(dsm + O_LG) + tid * 8;
        float lg[8];
        #pragma unroll
        for (int e = 0; e < 8; e++) lg[e] = lp[e];
        int i1 = 0; float m1 = lg[0];
        #pragma unroll
        for (int e = 1; e < 8; e++) if (lg[e] > m1) { m1 = lg[e]; i1 = e; }
        int i2 = -1; float m2 = -3.4e38f;
        #pragma unroll
        for (int e = 0; e < 8; e++) if (e != i1 && lg[e] > m2) { m2 = lg[e]; i2 = e; }
        float p1 = 1.f / (1.f + __expf(m2 - m1));
        float p2 = 1.f - p1;
        float o[8];
        #pragma unroll
        for (int e = 0; e < 8; e++) o[e] = (e == i1) ? p1 : (e == i2) ? p2 : 0.f;
        float* op = out + ((size_t)blockIdx.x * BM + tid) * NEXP;
        *(float4*)op       = make_float4(o[0], o[1], o[2], o[3]);
        *(float4*)(op + 4) = make_float4(o[4], o[5], o[6], o[7]);
    }
}

// ---------------- launch --------------------------------------------------------
extern "C" void kernel_launch(void* const* d_in, const int* in_sizes, int n_in,
                              void* d_out, int out_size)
{
    (void)in_sizes; (void)n_in; (void)out_size;
    const float* hs     = (const float*)d_in[0];
    const float* w_down = (const float*)d_in[1];
    const float* w_up   = (const float*)d_in[2];
    const float* gamma  = (const float*)d_in[3];
    const float* beta   = (const float*)d_in[4];
    float* out = (float*)d_out;

    static int attr_done = 0;
    if (!attr_done) {
        cudaFuncSetAttribute(router_kernel, cudaFuncAttributeMaxDynamicSharedMemorySize, SMEM_TOTAL);
        attr_done = 1;
    }
    prep_kernel<<<BOT, THREADS>>>(w_down, gamma, beta);
    router_kernel<<<NBLK, THREADS, SMEM_TOTAL>>>(hs, w_up, out);
}

// round 14
// speedup vs baseline: 1.5827x; 1.0696x over previous
#include <cuda_runtime.h>
#include <cuda_bf16.h>
#include <math.h>
#include <stdint.h>

#define HIDDEN 2048
#define BOT    64
#define NEXP   8
#define NTOK   16384

#define BM       64
#define BK       64
#define NTILES   (HIDDEN / BK)       // 32
#define THREADS  256
#define NBLK     (NTOK / BM)         // 256

// ---------------- dynamic smem layout (byte offsets) ---------------------------
#define A_HI(b)   ((b) * 8192)                // 2 x 8KB (64 rows x 128B bf16)
#define A_LO(b)   (16384 + (b) * 8192)        // 2 x 8KB
#define O_PART    0                           // 16KB k-partials (reuses A_HI post-loop)
#define O_ZB      16384                       // 17408B z buffer [64][68] (reuses A_LO)
#define O_MU      33792                       // 64 f32
#define O_RS      34048
#define O_S       34304
#define O_T       34560
#define O_WUP     34816                       // 2KB raw w_up [8][64]
#define O_LG      36864                       // 2KB logits [64][8]
#define SMEM_TOTAL 38912
#define ZSTRIDE   68

#define SWZ128(off) ((off) ^ (((off) >> 3) & 0x70))

// ---------------- device scratch (no allocations allowed) ----------------------
// B in mma.sync fragment order: index = ((k16blk*8 + n8blk)*32 + lane)*2 + reg
__device__ uint32_t g_Bfh[128 * 8 * 32 * 2];   // 256KB hi fragments
__device__ uint32_t g_Bfl[128 * 8 * 32 * 2];   // 256KB lo fragments
__device__ float g_s[BOT];
__device__ float g_t[BOT];

// ---------------- PTX helpers ---------------------------------------------------
__device__ __forceinline__ uint32_t smem_u32(const void* p) {
    uint32_t a;
    asm("{ .reg .u64 t; cvta.to.shared.u64 t, %1; cvt.u32.u64 %0, t; }" : "=r"(a) : "l"(p));
    return a;
}
#define LDMX4(r, a) \
    asm volatile("ldmatrix.sync.aligned.m8n8.x4.shared.b16 {%0,%1,%2,%3}, [%4];" \
        : "=r"((r)[0]), "=r"((r)[1]), "=r"((r)[2]), "=r"((r)[3]) : "r"(a))

#define MMA16816(d, a, b0, b1) \
    asm volatile("mma.sync.aligned.m16n8k16.row.col.f32.bf16.bf16.f32 " \
        "{%0,%1,%2,%3}, {%4,%5,%6,%7}, {%8,%9}, {%0,%1,%2,%3};" \
        : "+f"((d)[0]), "+f"((d)[1]), "+f"((d)[2]), "+f"((d)[3]) \
        : "r"((a)[0]), "r"((a)[1]), "r"((a)[2]), "r"((a)[3]), "r"(b0), "r"(b1))

// ---------------- prep: G = gamma*W -> bf16 hi/lo in FRAGMENT order -------------
__global__ void prep_kernel(const float* __restrict__ w_down,
                            const float* __restrict__ gamma,
                            const float* __restrict__ beta)
{
    __shared__ float red_s[8], red_t[8];
    const int n   = blockIdx.x;           // 0..63
    const int tid = threadIdx.x;          // 256
    const int k0  = tid * 8;

    float w[8], gv[8], bv[8];
    *(float4*)&w[0]  = *(const float4*)(w_down + n * HIDDEN + k0);
    *(float4*)&w[4]  = *(const float4*)(w_down + n * HIDDEN + k0 + 4);
    *(float4*)&gv[0] = *(const float4*)(gamma + k0);
    *(float4*)&gv[4] = *(const float4*)(gamma + k0 + 4);
    *(float4*)&bv[0] = *(const float4*)(beta + k0);
    *(float4*)&bv[4] = *(const float4*)(beta + k0 + 4);

    float ps = 0.f, pt = 0.f;
    uint32_t hw[4], lw[4];
    #pragma unroll
    for (int p = 0; p < 4; p++) {
        float g0 = gv[2*p] * w[2*p];
        float g1 = gv[2*p+1] * w[2*p+1];
        ps += g0 + g1;
        pt = fmaf(bv[2*p], w[2*p], pt);
        pt = fmaf(bv[2*p+1], w[2*p+1], pt);
        __nv_bfloat162 h = __floats2bfloat162_rn(g0, g1);
        float r0 = g0 - __bfloat162float(h.x);
        float r1 = g1 - __bfloat162float(h.y);
        __nv_bfloat162 l = __floats2bfloat162_rn(r0, r1);
        hw[p] = *(uint32_t*)&h;
        lw[p] = *(uint32_t*)&l;
    }
    {
        const int k16  = k0 >> 4;
        const int n8   = n >> 3;
        const int l0   = (n & 7) * 4;
        const int reg  = (k0 >> 3) & 1;
        const int base = ((k16 * 8 + n8) * 32 + l0) * 2 + reg;
        #pragma unroll
        for (int p = 0; p < 4; p++) {
            g_Bfh[base + p * 2] = hw[p];
            g_Bfl[base + p * 2] = lw[p];
        }
    }

    #pragma unroll
    for (int o = 16; o > 0; o >>= 1) {
        ps += __shfl_xor_sync(0xffffffffu, ps, o);
        pt += __shfl_xor_sync(0xffffffffu, pt, o);
    }
    int wi = tid >> 5, lane = tid & 31;
    if (lane == 0) { red_s[wi] = ps; red_t[wi] = pt; }
    __syncthreads();
    if (tid == 0) {
        float ss = 0.f, tt = 0.f;
        #pragma unroll
        for (int i = 0; i < 8; i++) { ss += red_s[i]; tt += red_t[i]; }
        g_s[n] = ss; g_t[n] = tt;
    }
}

// ---------------- main fused HMMA kernel ----------------------------------------
extern __shared__ char dsm[];

__global__ __launch_bounds__(THREADS, 2)
void router_kernel(const float* __restrict__ H,      // [16384][2048]
                   const float* __restrict__ w_up,   // [8][64]
                   float* __restrict__ out)          // [16384][8]
{
    const uint32_t sb  = smem_u32(dsm);
    const int tid  = threadIdx.x;
    const int wid  = tid >> 5;
    const int lane = tid & 31;
    const int pos  = wid & 3;             // warp position: 2m x 2n
    const int wm   = pos & 1;             // rows wm*32..+32
    const int wn   = pos >> 1;            // cols wn*32..+32
    const int kh   = wid >> 2;            // k-half within tile

    // small tables
    ((float*)(dsm + O_WUP))[tid]       = w_up[tid];
    ((float*)(dsm + O_WUP))[tid + 256] = w_up[tid + 256];
    if (tid < BOT) {
        ((float*)(dsm + O_S))[tid] = g_s[tid];
        ((float*)(dsm + O_T))[tid] = g_t[tid];
    }

    // A geometry: 4 float4/thread/tile; rows lrow+16j, k quad (tid&15)
    const int lrow = tid >> 4;
    const float* Hbase = H + ((size_t)blockIdx.x * BM + lrow) * HIDDEN + (tid & 15) * 4;
    const uint32_t sts_sw = SWZ128((uint32_t)(lrow * 128 + (tid & 15) * 8));

    // Hoisted A-LDSM offsets: SWZ128(row*128 + kb) == (SWZ128(row*128) ^ half16) ^ ks
    const uint32_t half16 = (uint32_t)((lane >> 4) * 16);
    uint32_t aoff[2];
    #pragma unroll
    for (int mi = 0; mi < 2; mi++)
        aoff[mi] = SWZ128((uint32_t)((wm * 32 + mi * 16 + (lane & 15)) * 128)) ^ half16;

    // B fragment base for this warp (per tile: + t*2048 words)
    const uint32_t bfbase = (uint32_t)(((kh * 2) * 8 + wn * 4) * 32 + lane) * 2;

    float acc[2][4][4];                  // [mi][n8][reg] for 32x32 warp tile
    #pragma unroll
    for (int mi = 0; mi < 2; mi++)
        #pragma unroll
        for (int ni = 0; ni < 4; ni++)
            #pragma unroll
            for (int r = 0; r < 4; r++) acc[mi][ni][r] = 0.f;

    float psum[4] = {0.f, 0.f, 0.f, 0.f};
    float psq[4]  = {0.f, 0.f, 0.f, 0.f};
    float4 pf[4];
    uint2 bh2[2][4], bl2[2][4];          // B fragments, pipelined one tile ahead

    // ---- prologue: A0 -> regs -> convert -> smem(0); A1 -> pf; B(0) -> regs ----
    #pragma unroll
    for (int j = 0; j < 4; j++)
        pf[j] = *(const float4*)(Hbase + (size_t)j * 16 * HIDDEN);
    #pragma unroll
    for (int j = 0; j < 4; j++) {
        float4 v = pf[j];
        psum[j] += (v.x + v.y) + (v.z + v.w);
        psq[j]  = fmaf(v.x, v.x, psq[j]); psq[j] = fmaf(v.y, v.y, psq[j]);
        psq[j]  = fmaf(v.z, v.z, psq[j]); psq[j] = fmaf(v.w, v.w, psq[j]);
        __nv_bfloat162 h01 = __floats2bfloat162_rn(v.x, v.y);
        __nv_bfloat162 h23 = __floats2bfloat162_rn(v.z, v.w);
        float rx = v.x - __bfloat162float(h01.x);
        float ry = v.y - __bfloat162float(h01.y);
        float rz = v.z - __bfloat162float(h23.x);
        float rw = v.w - __bfloat162float(h23.y);
        __nv_bfloat162 l01 = __floats2bfloat162_rn(rx, ry);
        __nv_bfloat162 l23 = __floats2bfloat162_rn(rz, rw);
        uint32_t sw = sts_sw + (uint32_t)(j * 2048);
        *(uint2*)(dsm + A_HI(0) + sw) = make_uint2(*(uint32_t*)&h01, *(uint32_t*)&h23);
        *(uint2*)(dsm + A_LO(0) + sw) = make_uint2(*(uint32_t*)&l01, *(uint32_t*)&l23);
    }
    #pragma unroll
    for (int j = 0; j < 4; j++)
        pf[j] = *(const float4*)(Hbase + BK + (size_t)j * 16 * HIDDEN);
    #pragma unroll
    for (int ss = 0; ss < 2; ss++) {
        const uint32_t o = bfbase + (uint32_t)ss * 512;
        #pragma unroll
        for (int j = 0; j < 4; j++) {
            bh2[ss][j] = *(const uint2*)&g_Bfh[o + j * 64];
            bl2[ss][j] = *(const uint2*)&g_Bfl[o + j * 64];
        }
    }
    __syncthreads();            // tile 0 A visible

    #pragma unroll 1
    for (int t = 0; t < NTILES; t++) {
        const int buf = t & 1, nb = buf ^ 1;
        // ---- MMA phase for tile t on buf (3-pass hi/lo, split-k), B already in regs
        {
            const uint32_t ab_hi = sb + A_HI(buf), ab_lo = sb + A_LO(buf);
            #pragma unroll
            for (int ss = 0; ss < 2; ss++) {
                const uint32_t ks = (uint32_t)(kh * 64 + ss * 32);
                uint32_t ah[2][4], al[2][4];
                #pragma unroll
                for (int mi = 0; mi < 2; mi++) {
                    LDMX4(ah[mi], ab_hi + (aoff[mi] ^ ks));
                    LDMX4(al[mi], ab_lo + (aoff[mi] ^ ks));
                }
                #pragma unroll
                for (int mi = 0; mi < 2; mi++)
                    #pragma unroll
                    for (int ni = 0; ni < 4; ni++) {
                        MMA16816(acc[mi][ni], ah[mi], bh2[ss][ni].x, bh2[ss][ni].y);
                        MMA16816(acc[mi][ni], ah[mi], bl2[ss][ni].x, bl2[ss][ni].y);
                        MMA16816(acc[mi][ni], al[mi], bh2[ss][ni].x, bh2[ss][ni].y);
                    }
            }
        }
        // ---- load B fragments for tile t+1 (pre-barrier: huge latency cover) ----
        if (t + 1 < NTILES) {
            const uint32_t tb = bfbase + (uint32_t)(t + 1) * 2048;
            #pragma unroll
            for (int ss = 0; ss < 2; ss++) {
                const uint32_t o = tb + (uint32_t)ss * 512;
                #pragma unroll
                for (int j = 0; j < 4; j++) {
                    bh2[ss][j] = *(const uint2*)&g_Bfh[o + j * 64];
                    bl2[ss][j] = *(const uint2*)&g_Bfl[o + j * 64];
                }
            }
        }
        // ---- convert A_{t+1} -> nb (overlaps tensor work of tile t) ----
        if (t + 1 < NTILES) {
            #pragma unroll
            for (int j = 0; j < 4; j++) {
                float4 v = pf[j];
                psum[j] += (v.x + v.y) + (v.z + v.w);
                psq[j]  = fmaf(v.x, v.x, psq[j]); psq[j] = fmaf(v.y, v.y, psq[j]);
                psq[j]  = fmaf(v.z, v.z, psq[j]); psq[j] = fmaf(v.w, v.w, psq[j]);
                __nv_bfloat162 h01 = __floats2bfloat162_rn(v.x, v.y);
                __nv_bfloat162 h23 = __floats2bfloat162_rn(v.z, v.w);
                float rx = v.x - __bfloat162float(h01.x);
                float ry = v.y - __bfloat162float(h01.y);
                float rz = v.z - __bfloat162float(h23.x);
                float rw = v.w - __bfloat162float(h23.y);
                __nv_bfloat162 l01 = __floats2bfloat162_rn(rx, ry);
                __nv_bfloat162 l23 = __floats2bfloat162_rn(rz, rw);
                uint32_t sw = sts_sw + (uint32_t)(j * 2048);
                *(uint2*)(dsm + A_HI(nb) + sw) = make_uint2(*(uint32_t*)&h01, *(uint32_t*)&h23);
                *(uint2*)(dsm + A_LO(nb) + sw) = make_uint2(*(uint32_t*)&l01, *(uint32_t*)&l23);
            }
        }
        // ---- prefetch A_{t+2} f32 (pf free; >1 iteration of slack) ----
        if (t + 2 < NTILES) {
            const float* hp = Hbase + (t + 2) * BK;
            #pragma unroll
            for (int j = 0; j < 4; j++)
                pf[j] = *(const float4*)(hp + (size_t)j * 16 * HIDDEN);
        }
        __syncthreads();            // tile t A reads done; tile t+1 A visible
    }

    // ---- kh=1 warps dump k-partials (once per CTA) ----
    if (kh == 1) {
        float* pp = (float*)(dsm + O_PART) + pos * 1024;
        #pragma unroll
        for (int mi = 0; mi < 2; mi++)
            #pragma unroll
            for (int ni = 0; ni < 4; ni++)
                #pragma unroll
                for (int r = 0; r < 4; r++)
                    pp[((mi * 4 + ni) * 4 + r) * 32 + lane] = acc[mi][ni][r];
    }

    // ---- LN stats: groups of 16 consecutive lanes share a row ----
    #pragma unroll
    for (int o = 1; o < 16; o <<= 1) {
        #pragma unroll
        for (int j = 0; j < 4; j++) {
            psum[j] += __shfl_xor_sync(0xffffffffu, psum[j], o);
            psq[j]  += __shfl_xor_sync(0xffffffffu, psq[j], o);
        }
    }
    if ((tid & 15) == 0) {
        #pragma unroll
        for (int j = 0; j < 4; j++) {
            int row = j * 16 + lrow;
            float mu  = psum[j] * (1.f / HIDDEN);
            float var = psq[j] * (1.f / HIDDEN) - mu * mu;
            ((float*)(dsm + O_MU))[row] = mu;
            ((float*)(dsm + O_RS))[row] = rsqrtf(var + 1e-5f);
        }
    }
    __syncthreads();

    // ---- kh=0 warps: merge partials, LN-correct + SiLU -> z buffer ----
    if (kh == 0) {
        float* zb = (float*)(dsm + O_ZB);    // [64][68]
        const float* pp  = (const float*)(dsm + O_PART) + pos * 1024;
        const float* muA = (const float*)(dsm + O_MU);
        const float* rsA = (const float*)(dsm + O_RS);
        const float* sA  = (const float*)(dsm + O_S);
        const float* tA  = (const float*)(dsm + O_T);
        #pragma unroll
        for (int mi = 0; mi < 2; mi++) {
            int r0 = wm * 32 + mi * 16 + (lane >> 2);
            float mu0 = muA[r0], rs0 = rsA[r0];
            float mu1 = muA[r0 + 8], rs1 = rsA[r0 + 8];
            #pragma unroll
            for (int ni = 0; ni < 4; ni++) {
                const float* pf4 = pp + ((mi * 4 + ni) * 4) * 32 + lane;
                float a0 = acc[mi][ni][0] + pf4[0];
                float a1 = acc[mi][ni][1] + pf4[32];
                float a2 = acc[mi][ni][2] + pf4[64];
                float a3 = acc[mi][ni][3] + pf4[96];
                int c0 = wn * 32 + ni * 8 + (lane & 3) * 2;
                float s0 = sA[c0], s1 = sA[c0 + 1];
                float t0 = tA[c0], t1 = tA[c0 + 1];
                float p00 = rs0 * (a0 - mu0 * s0) + t0;
                float p01 = rs0 * (a1 - mu0 * s1) + t1;
                float p10 = rs1 * (a2 - mu1 * s0) + t0;
                float p11 = rs1 * (a3 - mu1 * s1) + t1;
                float z00 = p00 / (1.f + __expf(-p00));
                float z01 = p01 / (1.f + __expf(-p01));
                float z10 = p10 / (1.f + __expf(-p10));
                float z11 = p11 / (1.f + __expf(-p11));
                *(float2*)&zb[r0 * ZSTRIDE + c0]       = make_float2(z00, z01);
                *(float2*)&zb[(r0 + 8) * ZSTRIDE + c0] = make_float2(z10, z11);
            }
        }
    }
    __syncthreads();

    // ---- router GEMM: thread = (token m, expert pair eg) ----
    {
        const int m = tid & 63, eg = tid >> 6;
        const float* zr = (const float*)(dsm + O_ZB) + m * ZSTRIDE;
        const float* w0 = (const float*)(dsm + O_WUP) + eg * 128;
        const float* w1 = w0 + 64;
        float l0 = 0.f, l1 = 0.f;
        #pragma unroll
        for (int d4 = 0; d4 < 16; d4++) {
            float4 zv = ((const float4*)zr)[d4];
            float4 wa = ((const float4*)w0)[d4];
            float4 wb = ((const float4*)w1)[d4];
            l0 = fmaf(zv.x, wa.x, l0); l0 = fmaf(zv.y, wa.y, l0);
            l0 = fmaf(zv.z, wa.z, l0); l0 = fmaf(zv.w, wa.w, l0);
            l1 = fmaf(zv.x, wb.x, l1); l1 = fmaf(zv.y, wb.y, l1);
            l1 = fmaf(zv.z, wb.z, l1); l1 = fmaf(zv.w, wb.w, l1);
        }
        ((float*)(dsm + O_LG))[m * 8 + eg * 2]     = l0;
        ((float*)(dsm + O_LG))[m * 8 + eg * 2 + 1] = l1;
    }
    __syncthreads();

    // ---- top-2 softmax (first-index tie-break matches jax.lax.top_k) ----
    if (tid < BM) {
        const float* lp = (const float*)(dsm + O_LG) + tid * 8;
        float lg[8];
        #pragma unroll
        for (int e = 0; e < 8; e++) lg[e] = lp[e];
        int i1 = 0; float m1 = lg[0];
        #pragma unroll
        for (int e = 1; e < 8; e++) if (lg[e] > m1) { m1 = lg[e]; i1 = e; }
        int i2 = -1; float m2 = -3.4e38f;
        #pragma unroll
        for (int e = 0; e < 8; e++) if (e != i1 && lg[e] > m2) { m2 = lg[e]; i2 = e; }
        float p1 = 1.f / (1.f + __expf(m2 - m1));
        float p2 = 1.f - p1;
        float o[8];
        #pragma unroll
        for (int e = 0; e < 8; e++) o[e] = (e == i1) ? p1 : (e == i2) ? p2 : 0.f;
        float* op = out + ((size_t)blockIdx.x * BM + tid) * NEXP;
        *(float4*)op       = make_float4(o[0], o[1], o[2], o[3]);
        *(float4*)(op + 4) = make_float4(o[4], o[5], o[6], o[7]);
    }
}

// ---------------- launch --------------------------------------------------------
extern "C" void kernel_launch(void* const* d_in, const int* in_sizes, int n_in,
                              void* d_out, int out_size)
{
    (void)in_sizes; (void)n_in; (void)out_size;
    const float* hs     = (const float*)d_in[0];
    const float* w_down = (const float*)d_in[1];
    const float* w_up   = (const float*)d_in[2];
    const float* gamma  = (const float*)d_in[3];
    const float* beta   = (const float*)d_in[4];
    float* out = (float*)d_out;

    static int attr_done = 0;
    if (!attr_done) {
        cudaFuncSetAttribute(router_kernel, cudaFuncAttributeMaxDynamicSharedMemorySize, SMEM_TOTAL);
        attr_done = 1;
    }
    prep_kernel<<<BOT, THREADS>>>(w_down, gamma, beta);
    router_kernel<<<NBLK, THREADS, SMEM_TOTAL>>>(hs, w_up, out);
}